// round 3
// baseline (speedup 1.0000x reference)
#include <cuda_runtime.h>
#include <cstdint>

// Problem constants (LIFLayer_50405736186152)
constexpr int BATCH = 64;
constexpr int T     = 1000;
constexpr int IN    = 512;
constexpr int OUT   = 512;
constexpr int M     = BATCH * T;   // 64000 rows of the input GEMM

// Scratch for the input-driven current cur[b,t,o] (device global: no cudaMalloc allowed)
__device__ float g_cur[(size_t)BATCH * T * OUT];

// ---------------------------------------------------------------------------
// TF32 helpers
// ---------------------------------------------------------------------------
__device__ __forceinline__ uint32_t f2tf32(float f) {
    uint32_t u;
    asm("cvt.rna.tf32.f32 %0, %1;" : "=r"(u) : "f"(f));
    return u;
}

__device__ __forceinline__ void mma_tf32(float* d, const uint32_t* a, const uint32_t* b) {
    asm volatile(
        "mma.sync.aligned.m16n8k8.row.col.f32.tf32.tf32.f32 "
        "{%0,%1,%2,%3}, {%4,%5,%6,%7}, {%8,%9}, {%0,%1,%2,%3};\n"
        : "+f"(d[0]), "+f"(d[1]), "+f"(d[2]), "+f"(d[3])
        : "r"(a[0]), "r"(a[1]), "r"(a[2]), "r"(a[3]),
          "r"(b[0]), "r"(b[1]));
}

// ---------------------------------------------------------------------------
// GEMM: g_cur[m, n] = sum_k X[m, k] * W[n, k] + bias[n]
// X: [M, 512] row-major, W: [512, 512] row-major (both K-contiguous).
// Block tile 128x128, K-tile 32, 256 threads (8 warps as 4(m) x 2(n)).
// Warp tile 32x64: 2 m-tiles x 8 n-tiles of m16n8k8.
// ---------------------------------------------------------------------------
constexpr int BKP = 36;   // padded K stride in smem (bank-conflict-free: bank = 4r+q)

__global__ void __launch_bounds__(256, 2)
gemm_tf32_kernel(const float* __restrict__ X,
                 const float* __restrict__ W,
                 const float* __restrict__ bias) {
    __shared__ uint32_t As[128 * BKP];
    __shared__ uint32_t Bs[128 * BKP];

    const int tid  = threadIdx.x;
    const int lane = tid & 31;
    const int warp = tid >> 5;
    const int warp_m = warp & 3;       // 0..3  -> 32 rows each
    const int warp_n = warp >> 2;      // 0..1  -> 64 cols each
    const int q = lane & 3;
    const int r = lane >> 2;

    const int mtile = blockIdx.y;      // 0..499
    const int ntile = blockIdx.x;      // 0..3

    const float* Ag = X + (size_t)mtile * 128 * IN;
    const float* Bg = W + (size_t)ntile * 128 * IN;

    float acc[2][8][4];
#pragma unroll
    for (int i = 0; i < 2; i++)
#pragma unroll
        for (int j = 0; j < 8; j++)
#pragma unroll
            for (int k = 0; k < 4; k++) acc[i][j][k] = 0.f;

    for (int kt = 0; kt < IN / 32; kt++) {
        const int k0 = kt * 32;
        __syncthreads();
        // Stage A and B tiles (128 rows x 32 k), converting to tf32.
#pragma unroll
        for (int i = 0; i < 4; i++) {
            int id  = tid + i * 256;       // 0..1023 float4 slots
            int row = id >> 3;
            int c4  = (id & 7) * 4;
            float4 av = *(const float4*)(Ag + (size_t)row * IN + k0 + c4);
            uint32_t* da = &As[row * BKP + c4];
            da[0] = f2tf32(av.x); da[1] = f2tf32(av.y);
            da[2] = f2tf32(av.z); da[3] = f2tf32(av.w);
            float4 bv = *(const float4*)(Bg + (size_t)row * IN + k0 + c4);
            uint32_t* db = &Bs[row * BKP + c4];
            db[0] = f2tf32(bv.x); db[1] = f2tf32(bv.y);
            db[2] = f2tf32(bv.z); db[3] = f2tf32(bv.w);
        }
        __syncthreads();

#pragma unroll
        for (int ks = 0; ks < 4; ks++) {
            const int k8 = ks * 8;
            uint32_t afr[2][4];
#pragma unroll
            for (int mt = 0; mt < 2; mt++) {
                int m0 = warp_m * 32 + mt * 16;
                afr[mt][0] = As[(m0 + r) * BKP + k8 + q];
                afr[mt][1] = As[(m0 + 8 + r) * BKP + k8 + q];
                afr[mt][2] = As[(m0 + r) * BKP + k8 + q + 4];
                afr[mt][3] = As[(m0 + 8 + r) * BKP + k8 + q + 4];
            }
            uint32_t bfr[8][2];
#pragma unroll
            for (int nt = 0; nt < 8; nt++) {
                int n0 = warp_n * 64 + nt * 8;
                bfr[nt][0] = Bs[(n0 + r) * BKP + k8 + q];
                bfr[nt][1] = Bs[(n0 + r) * BKP + k8 + q + 4];
            }
#pragma unroll
            for (int mt = 0; mt < 2; mt++)
#pragma unroll
                for (int nt = 0; nt < 8; nt++)
                    mma_tf32(acc[mt][nt], afr[mt], bfr[nt]);
        }
    }

    // Epilogue: add bias, write cur
#pragma unroll
    for (int mt = 0; mt < 2; mt++) {
        int gm = mtile * 128 + warp_m * 32 + mt * 16 + r;
#pragma unroll
        for (int nt = 0; nt < 8; nt++) {
            int gn = ntile * 128 + warp_n * 64 + nt * 8 + 2 * q;
            float b0 = bias[gn];
            float b1 = bias[gn + 1];
            float2 v01 = make_float2(acc[mt][nt][0] + b0, acc[mt][nt][1] + b1);
            float2 v23 = make_float2(acc[mt][nt][2] + b0, acc[mt][nt][3] + b1);
            *(float2*)&g_cur[(size_t)gm * OUT + gn]       = v01;
            *(float2*)&g_cur[(size_t)(gm + 8) * OUT + gn] = v23;
        }
    }
}

// ---------------------------------------------------------------------------
// Sequential LIF scan. One CTA per batch element, one thread per neuron.
// Spike recurrence handled via dynamic sparsity: per-step spike index list in
// smem; with these statistics (threshold ~11 sigma) the list is empty so the
// recurrent matvec costs nothing, but the general path is implemented.
// ---------------------------------------------------------------------------
__global__ void __launch_bounds__(512, 1)
lif_scan_kernel(const float* __restrict__ R,      // recurrent [OUT, OUT] row-major
                const float* __restrict__ decay,  // [OUT]
                float* __restrict__ out) {
    const int b = blockIdx.x;
    const int o = threadIdx.x;

    __shared__ int s_cnt[2];
    __shared__ int s_idx[2][OUT];
    if (o < 2) s_cnt[o] = 0;

    const float kd  = decay[o];
    const float omd = 1.0f - kd;

    const float* curp = g_cur + (size_t)b * T * OUT + o;
    float* outs = out + (size_t)b * T * OUT + o;                               // zs
    float* vful = out + (size_t)BATCH * T * OUT + (size_t)b * (T + 1) * OUT + o; // v_full
    float* zful = vful + (size_t)BATCH * (T + 1) * OUT;                          // z_full

    // t = 0 initial-state slices
    vful[0] = 0.0f;
    zful[0] = 0.0f;

    float v = 0.0f, z = 0.0f;
    int cnt_prev = 0;
    __syncthreads();   // s_cnt init + before first atomicAdd

    float cur_next = curp[0];
    for (int t = 0; t < T; t++) {
        float c = cur_next;
        if (t + 1 < T) cur_next = curp[(size_t)(t + 1) * OUT];  // prefetch

        float soma = c;
        if (cnt_prev > 0) {
            const int* lst = s_idx[(t ^ 1) & 1];  // list produced at step t-1
            for (int j = 0; j < cnt_prev; j++)
                soma += R[(size_t)o * OUT + lst[j]];
        }
        v = v * (1.0f - z);          // detached reset
        v = kd * v + omd * soma;
        z = (v >= 1.0f) ? 1.0f : 0.0f;

        outs[(size_t)t * OUT]       = z;
        vful[(size_t)(t + 1) * OUT] = v;
        zful[(size_t)(t + 1) * OUT] = z;

        const int par = t & 1;
        if (z != 0.0f) {
            int p = atomicAdd(&s_cnt[par], 1);
            s_idx[par][p] = o;
        }
        if (o == 0) s_cnt[par ^ 1] = 0;          // recycle consumed counter
        cnt_prev = __syncthreads_count(z != 0.0f);
    }
}

// ---------------------------------------------------------------------------
// Launch
// ---------------------------------------------------------------------------
extern "C" void kernel_launch(void* const* d_in, const int* in_sizes, int n_in,
                              void* d_out, int out_size) {
    const float* x    = (const float*)d_in[0];  // [B, T, IN]
    const float* w    = (const float*)d_in[1];  // [OUT, IN]
    const float* bias = (const float*)d_in[2];  // [OUT]
    const float* rec  = (const float*)d_in[3];  // [OUT, OUT]
    const float* dec  = (const float*)d_in[4];  // [OUT]
    float* out = (float*)d_out;

    dim3 ggrid(OUT / 128, M / 128);   // (4, 500)
    gemm_tf32_kernel<<<ggrid, 256>>>(x, w, bias);
    lif_scan_kernel<<<BATCH, 512>>>(rec, dec, out);
}

// round 5
// speedup vs baseline: 2.4501x; 2.4501x over previous
#include <cuda_runtime.h>
#include <cstdint>

// Problem constants (LIFLayer_50405736186152)
constexpr int BATCH = 64;
constexpr int T     = 1000;
constexpr int IN    = 512;
constexpr int OUT   = 512;
constexpr int M     = BATCH * T;   // 64000 rows of the input GEMM

// Scratch for the input-driven current cur[b,t,o] (device global: no cudaMalloc allowed)
__device__ float g_cur[(size_t)BATCH * T * OUT];

// ---------------------------------------------------------------------------
// TF32 helpers
// ---------------------------------------------------------------------------
__device__ __forceinline__ uint32_t f2tf32(float f) {
    uint32_t u;
    asm("cvt.rna.tf32.f32 %0, %1;" : "=r"(u) : "f"(f));
    return u;
}

__device__ __forceinline__ void mma_tf32(float* d, const uint32_t* a, const uint32_t* b) {
    asm volatile(
        "mma.sync.aligned.m16n8k8.row.col.f32.tf32.tf32.f32 "
        "{%0,%1,%2,%3}, {%4,%5,%6,%7}, {%8,%9}, {%0,%1,%2,%3};\n"
        : "+f"(d[0]), "+f"(d[1]), "+f"(d[2]), "+f"(d[3])
        : "r"(a[0]), "r"(a[1]), "r"(a[2]), "r"(a[3]),
          "r"(b[0]), "r"(b[1]));
}

// ---------------------------------------------------------------------------
// GEMM: g_cur[m, n] = sum_k X[m, k] * W[n, k] + bias[n]
// X: [M, 512] row-major, W: [512, 512] row-major (both K-contiguous).
// Block tile 128x128, K-tile 32, 256 threads (8 warps as 4(m) x 2(n)).
// Warp tile 32x64: 2 m-tiles x 8 n-tiles of m16n8k8.
// ---------------------------------------------------------------------------
constexpr int BKP = 36;   // padded K stride in smem (bank-conflict-free: bank = 4r+q)

__global__ void __launch_bounds__(256, 2)
gemm_tf32_kernel(const float* __restrict__ X,
                 const float* __restrict__ W,
                 const float* __restrict__ bias) {
    __shared__ uint32_t As[128 * BKP];
    __shared__ uint32_t Bs[128 * BKP];

    const int tid  = threadIdx.x;
    const int lane = tid & 31;
    const int warp = tid >> 5;
    const int warp_m = warp & 3;       // 0..3  -> 32 rows each
    const int warp_n = warp >> 2;      // 0..1  -> 64 cols each
    const int q = lane & 3;
    const int r = lane >> 2;

    const int mtile = blockIdx.y;      // 0..499
    const int ntile = blockIdx.x;      // 0..3

    const float* Ag = X + (size_t)mtile * 128 * IN;
    const float* Bg = W + (size_t)ntile * 128 * IN;

    float acc[2][8][4];
#pragma unroll
    for (int i = 0; i < 2; i++)
#pragma unroll
        for (int j = 0; j < 8; j++)
#pragma unroll
            for (int k = 0; k < 4; k++) acc[i][j][k] = 0.f;

    for (int kt = 0; kt < IN / 32; kt++) {
        const int k0 = kt * 32;
        __syncthreads();
        // Stage A and B tiles (128 rows x 32 k), converting to tf32.
#pragma unroll
        for (int i = 0; i < 4; i++) {
            int id  = tid + i * 256;       // 0..1023 float4 slots
            int row = id >> 3;
            int c4  = (id & 7) * 4;
            float4 av = *(const float4*)(Ag + (size_t)row * IN + k0 + c4);
            uint32_t* da = &As[row * BKP + c4];
            da[0] = f2tf32(av.x); da[1] = f2tf32(av.y);
            da[2] = f2tf32(av.z); da[3] = f2tf32(av.w);
            float4 bv = *(const float4*)(Bg + (size_t)row * IN + k0 + c4);
            uint32_t* db = &Bs[row * BKP + c4];
            db[0] = f2tf32(bv.x); db[1] = f2tf32(bv.y);
            db[2] = f2tf32(bv.z); db[3] = f2tf32(bv.w);
        }
        __syncthreads();

#pragma unroll
        for (int ks = 0; ks < 4; ks++) {
            const int k8 = ks * 8;
            uint32_t afr[2][4];
#pragma unroll
            for (int mt = 0; mt < 2; mt++) {
                int m0 = warp_m * 32 + mt * 16;
                afr[mt][0] = As[(m0 + r) * BKP + k8 + q];
                afr[mt][1] = As[(m0 + 8 + r) * BKP + k8 + q];
                afr[mt][2] = As[(m0 + r) * BKP + k8 + q + 4];
                afr[mt][3] = As[(m0 + 8 + r) * BKP + k8 + q + 4];
            }
            uint32_t bfr[8][2];
#pragma unroll
            for (int nt = 0; nt < 8; nt++) {
                int n0 = warp_n * 64 + nt * 8;
                bfr[nt][0] = Bs[(n0 + r) * BKP + k8 + q];
                bfr[nt][1] = Bs[(n0 + r) * BKP + k8 + q + 4];
            }
#pragma unroll
            for (int mt = 0; mt < 2; mt++)
#pragma unroll
                for (int nt = 0; nt < 8; nt++)
                    mma_tf32(acc[mt][nt], afr[mt], bfr[nt]);
        }
    }

    // Epilogue: add bias, write cur
#pragma unroll
    for (int mt = 0; mt < 2; mt++) {
        int gm = mtile * 128 + warp_m * 32 + mt * 16 + r;
#pragma unroll
        for (int nt = 0; nt < 8; nt++) {
            int gn = ntile * 128 + warp_n * 64 + nt * 8 + 2 * q;
            float b0 = bias[gn];
            float b1 = bias[gn + 1];
            float2 v01 = make_float2(acc[mt][nt][0] + b0, acc[mt][nt][1] + b1);
            float2 v23 = make_float2(acc[mt][nt][2] + b0, acc[mt][nt][3] + b1);
            *(float2*)&g_cur[(size_t)gm * OUT + gn]       = v01;
            *(float2*)&g_cur[(size_t)(gm + 8) * OUT + gn] = v23;
        }
    }
}

// ---------------------------------------------------------------------------
// Sequential LIF scan. One CTA per batch element, one thread per neuron.
//
// Round-3 fix: the previous version was latency-bound (710 ns/step) because
// each thread held exactly ONE outstanding cur load across the per-step
// barrier. Now a PF-deep register ring keeps PF loads in flight per thread
// (MLP_eff = PF), and the common no-spike path does zero atomics / zero
// shared-counter maintenance — just one BAR.RED (__syncthreads_count) per
// step. Spike index list is built lazily only on steps that follow a spike.
// ---------------------------------------------------------------------------
constexpr int PF = 8;   // prefetch depth; T % PF == 0

__global__ void __launch_bounds__(512, 1)
lif_scan_kernel(const float* __restrict__ R,      // recurrent [OUT, OUT] row-major
                const float* __restrict__ decay,  // [OUT]
                float* __restrict__ out) {
    const int b = blockIdx.x;
    const int o = threadIdx.x;

    __shared__ int s_cnt;
    __shared__ int s_idx[OUT];
    if (o == 0) s_cnt = 0;

    const float kd  = decay[o];
    const float omd = 1.0f - kd;

    const float* curp = g_cur + (size_t)b * T * OUT + o;
    float* outs = out + (size_t)b * T * OUT + o;                                 // zs
    float* vful = out + (size_t)BATCH * T * OUT + (size_t)b * (T + 1) * OUT + o; // v_full
    float* zful = vful + (size_t)BATCH * (T + 1) * OUT;                          // z_full

    // t = 0 initial-state slices
    vful[0] = 0.0f;
    zful[0] = 0.0f;

    // Fill the prefetch ring: PF outstanding loads per thread.
    float buf[PF];
#pragma unroll
    for (int i = 0; i < PF; i++)
        buf[i] = __ldcs(curp + (size_t)i * OUT);

    float v = 0.0f, z = 0.0f;
    int cnt_prev = 0;
    __syncthreads();   // covers s_cnt init

    for (int tb = 0; tb < T; tb += PF) {
#pragma unroll
        for (int u = 0; u < PF; u++) {
            const int t = tb + u;
            float c = buf[u];
            // refill this slot PF steps ahead (keeps PF loads in flight)
            if (t + PF < T)
                buf[u] = __ldcs(curp + (size_t)(t + PF) * OUT);

            float soma = c;
            if (cnt_prev > 0) {           // uniform branch (from BAR.RED)
                // Lazily build the spike list from last step's z.
                if (z != 0.0f) {
                    int p = atomicAdd(&s_cnt, 1);
                    s_idx[p] = o;
                }
                __syncthreads();          // list complete
                for (int j = 0; j < cnt_prev; j++)
                    soma += R[(size_t)o * OUT + s_idx[j]];
                __syncthreads();          // all reads done before list reuse
                if (o == 0) s_cnt = 0;    // ordered vs next atomicAdd by the
                                          // BAR.RED at the end of this step
            }

            v = v * (1.0f - z);           // detached reset
            v = kd * v + omd * soma;
            z = (v >= 1.0f) ? 1.0f : 0.0f;

            __stcs(outs + (size_t)t * OUT, z);
            __stcs(vful + (size_t)(t + 1) * OUT, v);
            __stcs(zful + (size_t)(t + 1) * OUT, z);

            cnt_prev = __syncthreads_count(z != 0.0f);
        }
    }
}

// ---------------------------------------------------------------------------
// Launch
// ---------------------------------------------------------------------------
extern "C" void kernel_launch(void* const* d_in, const int* in_sizes, int n_in,
                              void* d_out, int out_size) {
    const float* x    = (const float*)d_in[0];  // [B, T, IN]
    const float* w    = (const float*)d_in[1];  // [OUT, IN]
    const float* bias = (const float*)d_in[2];  // [OUT]
    const float* rec  = (const float*)d_in[3];  // [OUT, OUT]
    const float* dec  = (const float*)d_in[4];  // [OUT]
    float* out = (float*)d_out;

    dim3 ggrid(OUT / 128, M / 128);   // (4, 500)
    gemm_tf32_kernel<<<ggrid, 256>>>(x, w, bias);
    lif_scan_kernel<<<BATCH, 512>>>(rec, dec, out);
}